// round 9
// baseline (speedup 1.0000x reference)
#include <cuda_runtime.h>
#include <stdint.h>

// MultiIndexSelect via inverse permutation, two passes.
//
// to0|to1|to2 is a permutation of [0, 3L). Pass 1 builds
//   inv[to_s[j]] = (s << 20) | from_s[j]      (from < 500000 < 2^20)
// Pass 2 walks output rows IN ORDER: sequential inv read, random source
// gather, perfectly sequential 256B output stores (streaming, .cs).
// This trades the random-granule scatter writes (DRAM row-miss heavy) for
// one extra small pass.

#define D4 16              // float4s per row (D=64 floats = 256 B)
#define RPT 4
#define ROWS_PER_BLOCK 64

__device__ int g_inv[1200000];   // 3L scratch, 4.8 MB static (allowed)

// ---------------- Pass 1: build inverse permutation ----------------
__global__ void __launch_bounds__(256)
build_inv_kernel(
    const int* __restrict__ f0, const int* __restrict__ f1, const int* __restrict__ f2,
    const int* __restrict__ t0, const int* __restrict__ t1, const int* __restrict__ t2,
    int L, int blocks_per_seg)
{
    const int seg = blockIdx.x / blocks_per_seg;
    const int j = (blockIdx.x - seg * blocks_per_seg) * 256 + threadIdx.x;
    if (j >= L) return;

    const int* __restrict__ f = (seg == 0) ? f0 : (seg == 1) ? f1 : f2;
    const int* __restrict__ t = (seg == 0) ? t0 : (seg == 1) ? t1 : t2;

    int fr = __ldg(&f[j]);
    int to = __ldg(&t[j]);
    int val = (seg << 20) | fr;
    // scattered 4B store, evict-first (never re-read from L2 by this kernel)
    asm volatile("st.global.cs.b32 [%0], %1;" :: "l"(&g_inv[to]), "r"(val) : "memory");
}

// ---------------- Pass 2: ordered gather-copy ----------------
__device__ __forceinline__ void store_streaming(float4* p, float4 v) {
    asm volatile("st.global.cs.v4.f32 [%0], {%1, %2, %3, %4};"
                 :: "l"(p), "f"(v.x), "f"(v.y), "f"(v.z), "f"(v.w) : "memory");
}

__global__ void __launch_bounds__(256)
gather_ordered_kernel(
    const float4* __restrict__ m0,
    const float4* __restrict__ m1,
    const float4* __restrict__ m2,
    float4*       __restrict__ out)
{
    const int lane = threadIdx.x & (D4 - 1);              // 0..15
    const int rsub = threadIdx.x >> 4;                    // 0..15
    const int rbase = blockIdx.x * ROWS_PER_BLOCK + rsub; // rows rbase + 16*i

    // Phase 1: sequential inv reads (broadcast across the 16 lanes of a row)
    int id[RPT];
    #pragma unroll
    for (int i = 0; i < RPT; i++) {
        id[i] = __ldg(&g_inv[rbase + 16 * i]);
    }

    // Phase 2: front-batched random source gathers (MLP=4)
    float4 v[RPT];
    #pragma unroll
    for (int i = 0; i < RPT; i++) {
        int seg = id[i] >> 20;
        int fr  = id[i] & 0xFFFFF;
        const float4* __restrict__ src = (seg == 0) ? m0 : (seg == 1) ? m1 : m2;
        v[i] = __ldg(&src[(size_t)fr * D4 + lane]);
    }

    // Phase 3: perfectly sequential streaming stores (64 consecutive rows/block)
    #pragma unroll
    for (int i = 0; i < RPT; i++) {
        store_streaming(&out[(size_t)(rbase + 16 * i) * D4 + lane], v[i]);
    }
}

extern "C" void kernel_launch(void* const* d_in, const int* in_sizes, int n_in,
                              void* d_out, int out_size)
{
    const float4* m0 = (const float4*)d_in[0];
    const float4* m1 = (const float4*)d_in[1];
    const float4* m2 = (const float4*)d_in[2];
    const int* f0 = (const int*)d_in[3];
    const int* f1 = (const int*)d_in[4];
    const int* f2 = (const int*)d_in[5];
    const int* t0 = (const int*)d_in[6];
    const int* t1 = (const int*)d_in[7];
    const int* t2 = (const int*)d_in[8];
    float4* out = (float4*)d_out;

    int L = in_sizes[3];                              // 400000
    int blocks_per_seg = (L + 255) / 256;             // 1563
    build_inv_kernel<<<3 * blocks_per_seg, 256>>>(f0, f1, f2, t0, t1, t2,
                                                  L, blocks_per_seg);

    int total_rows = 3 * L;                           // 1.2M
    int blocks = total_rows / ROWS_PER_BLOCK;         // 18750 exact
    gather_ordered_kernel<<<blocks, 256>>>(m0, m1, m2, out);
}

// round 10
// speedup vs baseline: 1.1450x; 1.1450x over previous
#include <cuda_runtime.h>
#include <stdint.h>

// MultiIndexSelect: out[to_s[j]] = mat_s[from_s[j]] for s in {0,1,2}, j in [0,L)
// D = 64 floats = 16 float4 = 256 B per row.
//
// R10 = R3 structure (segment-phased blocks, block-uniform pointers, 16
// lanes/row, streaming .cs stores) with RPT=8 and a software-pipelined
// load/store schedule: 4 payload loads stay in flight while stores drain
// (each store is immediately backfilled by the next load). 128 rows/block,
// 3125 blocks/segment (exact: L=400000/128).

#define D4 16
#define RPT 8
#define ROWS_PER_BLOCK 128
#define BLOCKS_PER_SEG 3125   // L / ROWS_PER_BLOCK

__device__ __forceinline__ void store_streaming(float4* p, float4 v) {
    asm volatile("st.global.cs.v4.f32 [%0], {%1, %2, %3, %4};"
                 :: "l"(p), "f"(v.x), "f"(v.y), "f"(v.z), "f"(v.w) : "memory");
}

__global__ void __launch_bounds__(256)
multi_index_select_kernel(
    const float4* __restrict__ m0,
    const float4* __restrict__ m1,
    const float4* __restrict__ m2,
    const int*    __restrict__ f0,
    const int*    __restrict__ f1,
    const int*    __restrict__ f2,
    const int*    __restrict__ t0,
    const int*    __restrict__ t1,
    const int*    __restrict__ t2,
    float4*       __restrict__ out)
{
    // Block-uniform segment selection (uniform-register pointers)
    const int seg = blockIdx.x / BLOCKS_PER_SEG;          // 0, 1, 2
    const int segblk = blockIdx.x - seg * BLOCKS_PER_SEG;

    const float4* __restrict__ src = (seg == 0) ? m0 : (seg == 1) ? m1 : m2;
    const int*    __restrict__ fi  = (seg == 0) ? f0 : (seg == 1) ? f1 : f2;
    const int*    __restrict__ ti  = (seg == 0) ? t0 : (seg == 1) ? t1 : t2;

    const int lane = threadIdx.x & (D4 - 1);              // 0..15
    const int rsub = threadIdx.x >> 4;                    // 0..15
    const int rbase = segblk * ROWS_PER_BLOCK + rsub;     // rows: rbase + 16*i

    // Phase 1: batch all 8 index pairs (broadcast within 16-lane groups)
    int fr[RPT], to[RPT];
    #pragma unroll
    for (int i = 0; i < RPT; i++) {
        int r = rbase + 16 * i;
        fr[i] = __ldg(&fi[r]);
        to[i] = __ldg(&ti[r]);
    }

    // Phase 2+3: software pipeline, 4 payload loads in flight at all times.
    //   load v0..v3
    //   store v0 / load v4, store v1 / load v5, store v2 / load v6, store v3 / load v7
    //   store v4..v7
    float4 v[4];
    #pragma unroll
    for (int i = 0; i < 4; i++) {
        v[i] = __ldg(&src[(size_t)fr[i] * D4 + lane]);
    }
    #pragma unroll
    for (int i = 0; i < 4; i++) {
        float4 done = v[i];
        v[i] = __ldg(&src[(size_t)fr[i + 4] * D4 + lane]);   // backfill slot
        store_streaming(&out[(size_t)to[i] * D4 + lane], done);
    }
    #pragma unroll
    for (int i = 0; i < 4; i++) {
        store_streaming(&out[(size_t)to[i + 4] * D4 + lane], v[i]);
    }
}

extern "C" void kernel_launch(void* const* d_in, const int* in_sizes, int n_in,
                              void* d_out, int out_size)
{
    const float4* m0 = (const float4*)d_in[0];
    const float4* m1 = (const float4*)d_in[1];
    const float4* m2 = (const float4*)d_in[2];
    const int* f0 = (const int*)d_in[3];
    const int* f1 = (const int*)d_in[4];
    const int* f2 = (const int*)d_in[5];
    const int* t0 = (const int*)d_in[6];
    const int* t1 = (const int*)d_in[7];
    const int* t2 = (const int*)d_in[8];
    float4* out = (float4*)d_out;

    // 3 * 400000 rows / 128 rows per block = 9375 blocks exactly
    multi_index_select_kernel<<<3 * BLOCKS_PER_SEG, 256>>>(
        m0, m1, m2, f0, f1, f2, t0, t1, t2, out);
}